// round 5
// baseline (speedup 1.0000x reference)
#include <cuda_runtime.h>

// FIStateProbabilitiesPaulied: B=256, ND=4, NQ=3 -> D=8, L=64.
// Round 5: eigendecomposition ELIMINATED. Taylor-series propagator + per-direction
// vector Frechet recursion (8 threads/direction, shuffle-exchanged).
//   Kernel A (grid 256 x 512): pw, A=-iH build, w-series (8 lanes, shfl),
//                              64 directions x 8 rows -> h scratch.
//   Kernel B (grid 1024 x 128): Gram Ib = h^T h (redundant x4), stream I_k quarter + I_b.
// Output layout: I_k [256*4*64*4*64] then I_b [256*64*64].

#define NTAY 20

__device__ float g_hmat[256 * 512];   // [i][p(8)][k(64)]

// ======================= Kernel A: Taylor propagator + Jacobian =======================
__global__ __launch_bounds__(512)
void tay_kernel(const float* __restrict__ x,
                const float* __restrict__ kern,
                const float* __restrict__ bias)
{
    const int i = blockIdx.x;
    const int tid = threadIdx.x;   // 512 threads

    __shared__ float pw[64];
    __shared__ float Ar[8][8], Ai[8][8];          // A = -iH
    __shared__ float Wr[NTAY+1][8], Wi[NTAY+1][8]; // w_n = A^n e0 / n!
    __shared__ float sAmpR[8], sAmpI[8], sSip[8];

    // ---- Phase 1: pw = x@kernel + bias ----
    if (tid < 64) {
        float acc = bias[tid];
        #pragma unroll
        for (int d = 0; d < 4; ++d) acc += x[i*4+d] * kern[d*64+tid];
        pw[tid] = acc;
    }
    __syncthreads();

    // ---- Phase 2: build H analytically; store A = -iH (Ar=Hi, Ai=-Hr) ----
    if (tid < 64) {
        int r = tid >> 3, c = tid & 7, m = r ^ c;
        float hr = 0.0f, hi = 0.0f;
        #pragma unroll
        for (int sel = 0; sel < 8; ++sel) {
            int k = 0, ph = 0;
            #pragma unroll
            for (int q = 0; q < 3; ++q) {
                int bit = 2 - q;
                int mq = (m >> bit) & 1;
                int sq = (sel >> bit) & 1;
                int d = mq ? (sq ? 2 : 1) : (sq ? 3 : 0);
                k = (k << 2) | d;
                int rb = (r >> bit) & 1;
                if (d == 2) ph += rb ? 1 : 3;        // Y
                else if (d == 3) ph += rb ? 2 : 0;   // Z
            }
            float wv = pw[k];
            switch (ph & 3) {
                case 0: hr += wv; break;
                case 1: hi += wv; break;
                case 2: hr -= wv; break;
                default: hi -= wv; break;
            }
        }
        Ar[r][c] = hi;
        Ai[r][c] = -hr;
    }
    __syncthreads();

    // ---- Phase 3: w-series + amp on lanes 0-7 of warp 0 (shuffle matvec) ----
    if (tid < 8) {
        const int j = tid;
        float ar8[8], ai8[8];
        #pragma unroll
        for (int m = 0; m < 8; ++m) { ar8[m] = Ar[j][m]; ai8[m] = Ai[j][m]; }
        float wr = (j == 0) ? 1.0f : 0.0f, wi = 0.0f;
        Wr[0][j] = wr; Wi[0][j] = wi;
        float sumr = wr, sumi = wi;
        #pragma unroll
        for (int n = 1; n <= NTAY; ++n) {
            float accr = 0.f, acci = 0.f;
            #pragma unroll
            for (int m = 0; m < 8; ++m) {
                float xr = __shfl_sync(0x000000FFu, wr, m);
                float xi = __shfl_sync(0x000000FFu, wi, m);
                accr += ar8[m]*xr - ai8[m]*xi;
                acci += ar8[m]*xi + ai8[m]*xr;
            }
            float rn = 1.0f / (float)n;
            wr = accr * rn; wi = acci * rn;
            Wr[n][j] = wr; Wi[n][j] = wi;
            sumr += wr; sumi += wi;
        }
        float P = sumr*sumr + sumi*sumi;
        sAmpR[j] = sumr; sAmpI[j] = sumi;
        sSip[j] = rsqrtf(P);
    }
    __syncthreads();

    // ---- Phase 4: directional derivatives. thread = (k = tid>>3, r = tid&7) ----
    {
        const int k = tid >> 3;        // Pauli direction
        const int r = tid & 7;         // state component
        const int lane = tid & 31;
        const int base = lane & 24;    // 8-lane direction group within warp

        // Pauli k structure at row r: column r^mask, phase i^phv
        int d0 = (k>>4)&3, d1 = (k>>2)&3, d2 = k&3;
        int mask = ((d0==1||d0==2)?4:0) | ((d1==1||d1==2)?2:0) | ((d2==1||d2==2)?1:0);
        int ph = 0;
        {
            int rb2=(r>>2)&1, rb1=(r>>1)&1, rb0=r&1;
            if (d0==2) ph += rb2?1:3; else if (d0==3) ph += rb2?2:0;
            if (d1==2) ph += rb1?1:3; else if (d1==3) ph += rb1?2:0;
            if (d2==2) ph += rb0?1:3; else if (d2==3) ph += rb0?2:0;
        }
        const int phs = (ph + 3) & 3;        // extra *(-i) from dA = -i P_k
        const int rx = r ^ mask;

        float ar8[8], ai8[8];
        #pragma unroll
        for (int m = 0; m < 8; ++m) { ar8[m] = Ar[r][m]; ai8[m] = Ai[r][m]; }

        float phr = 0.f, phi_ = 0.f;   // phi_n (component r)
        float dsr = 0.f, dsi = 0.f;    // sum of phi_n

        #pragma unroll
        for (int n = 1; n <= NTAY; ++n) {
            // gather phi of own direction group
            float accr = 0.f, acci = 0.f;
            #pragma unroll
            for (int m = 0; m < 8; ++m) {
                float xr = __shfl_sync(0xFFFFFFFFu, phr,  base | m);
                float xi = __shfl_sync(0xFFFFFFFFu, phi_, base | m);
                accr += ar8[m]*xr - ai8[m]*xi;
                acci += ar8[m]*xi + ai8[m]*xr;
            }
            // sparse term: i^phs * w_{n-1}[r^mask]
            float wvr = Wr[n-1][rx], wvi = Wi[n-1][rx];
            float tr, ti;
            if      (phs == 0) { tr =  wvr; ti =  wvi; }
            else if (phs == 1) { tr = -wvi; ti =  wvr; }
            else if (phs == 2) { tr = -wvr; ti = -wvi; }
            else               { tr =  wvi; ti = -wvr; }
            float rn = 1.0f / (float)n;
            phr  = (accr + tr) * rn;
            phi_ = (acci + ti) * rn;
            dsr += phr; dsi += phi_;
        }

        // h[r][k] = 2 Re(conj(amp_r) * damp_r) / sqrt(P_r)
        float g = 2.0f * (sAmpR[r]*dsr + sAmpI[r]*dsi);
        g_hmat[(size_t)i*512 + r*64 + k] = g * sSip[r];
    }
}

// ======================= Kernel B: Gram + streaming store (quarter split) ==============
__global__ __launch_bounds__(128)
void out_kernel(const float* __restrict__ x,
                float* __restrict__ out)
{
    const int i = blockIdx.x >> 2;
    const int j = blockIdx.x & 3;
    const int tid = threadIdx.x;     // 128 threads

    __shared__ float hmat[8][64];
    __shared__ float Ib[64][64];

    // load hmat (512 floats = 128 float4)
    {
        const float4* hsrc = (const float4*)(g_hmat + (size_t)i*512);
        ((float4*)&hmat[0][0])[tid] = hsrc[tid];
    }
    float xj = x[i*4 + j];
    float sxx4[4];
    #pragma unroll
    for (int l = 0; l < 4; ++l) sxx4[l] = xj * x[i*4 + l];
    __syncthreads();

    // Ib = h^T h (rank-8), 32 entries/thread
    {
        int a = tid >> 1;
        int bb = (tid & 1) << 5;
        float ha[8];
        #pragma unroll
        for (int p = 0; p < 8; ++p) ha[p] = hmat[p][a];
        #pragma unroll
        for (int u = 0; u < 32; ++u) {
            int b = bb + u;
            float acc = 0.f;
            #pragma unroll
            for (int p = 0; p < 8; ++p) acc += ha[p]*hmat[p][b];
            Ib[a][b] = acc;
        }
    }
    __syncthreads();

    // write this j's I_k quarter: 4096 float4, 32/thread
    {
        float4* outk = (float4*)out + (size_t)i*16384 + (size_t)j*4096;
        const float4* ib4 = (const float4*)&Ib[0][0];
        #pragma unroll
        for (int u = 0; u < 32; ++u) {
            int idx = tid + 128*u;
            int b4 = idx & 15;
            int l  = (idx >> 4) & 3;
            int a  = idx >> 6;
            float sxx = sxx4[l];
            float4 v = ib4[a*16 + b4];
            v.x *= sxx; v.y *= sxx; v.z *= sxx; v.w *= sxx;
            outk[idx] = v;
        }
    }

    // block j==0 also writes I_b: 1024 float4, 8/thread
    if (j == 0) {
        float4* outb = (float4*)(out + (size_t)256*65536 + (size_t)i*4096);
        const float4* ib4 = (const float4*)&Ib[0][0];
        #pragma unroll
        for (int u = 0; u < 8; ++u) outb[tid + 128*u] = ib4[tid + 128*u];
    }
}

extern "C" void kernel_launch(void* const* d_in, const int* in_sizes, int n_in,
                              void* d_out, int out_size) {
    const float* x = nullptr; const float* k = nullptr; const float* b = nullptr;
    for (int t = 0; t < n_in; ++t) {
        if (in_sizes[t] == 1024 && !x) x = (const float*)d_in[t];
        else if (in_sizes[t] == 256 && !k) k = (const float*)d_in[t];
        else if (in_sizes[t] == 64 && !b) b = (const float*)d_in[t];
    }
    if (!x) x = (const float*)d_in[0];
    if (!k) k = (const float*)d_in[1];
    if (!b) b = (const float*)d_in[2];
    tay_kernel<<<256, 512>>>(x, k, b);
    out_kernel<<<1024, 128>>>(x, (float*)d_out);
}

// round 6
// speedup vs baseline: 1.6048x; 1.6048x over previous
#include <cuda_runtime.h>

// FIStateProbabilitiesPaulied: B=256, ND=4, NQ=3 -> D=8, L=64.
// Kernel A (grid 256 x 512): Taylor propagator + per-direction Frechet recursion -> h scratch.
// Kernel B (grid 1024 x 256): fused Gram+store: each thread owns one (a,b4) float4 of I_b,
//   computes it in registers from the hmat tile, emits 16 scaled I_k stores + 1 I_b store.
// Output layout: I_k [256*4*64*4*64] then I_b [256*64*64].

#define NTAY 20

__device__ float g_hmat[256 * 512];   // [i][p(8)][k(64)]

// ======================= Kernel A: Taylor propagator + Jacobian =======================
__global__ __launch_bounds__(512)
void tay_kernel(const float* __restrict__ x,
                const float* __restrict__ kern,
                const float* __restrict__ bias)
{
    const int i = blockIdx.x;
    const int tid = threadIdx.x;   // 512 threads

    __shared__ float pw[64];
    __shared__ float Ar[8][8], Ai[8][8];          // A = -iH
    __shared__ float Wr[NTAY+1][8], Wi[NTAY+1][8]; // w_n = A^n e0 / n!
    __shared__ float sAmpR[8], sAmpI[8], sSip[8];

    // ---- Phase 1: pw = x@kernel + bias ----
    if (tid < 64) {
        float acc = bias[tid];
        #pragma unroll
        for (int d = 0; d < 4; ++d) acc += x[i*4+d] * kern[d*64+tid];
        pw[tid] = acc;
    }
    __syncthreads();

    // ---- Phase 2: build H analytically; store A = -iH (Ar=Hi, Ai=-Hr) ----
    if (tid < 64) {
        int r = tid >> 3, c = tid & 7, m = r ^ c;
        float hr = 0.0f, hi = 0.0f;
        #pragma unroll
        for (int sel = 0; sel < 8; ++sel) {
            int k = 0, ph = 0;
            #pragma unroll
            for (int q = 0; q < 3; ++q) {
                int bit = 2 - q;
                int mq = (m >> bit) & 1;
                int sq = (sel >> bit) & 1;
                int d = mq ? (sq ? 2 : 1) : (sq ? 3 : 0);
                k = (k << 2) | d;
                int rb = (r >> bit) & 1;
                if (d == 2) ph += rb ? 1 : 3;        // Y
                else if (d == 3) ph += rb ? 2 : 0;   // Z
            }
            float wv = pw[k];
            switch (ph & 3) {
                case 0: hr += wv; break;
                case 1: hi += wv; break;
                case 2: hr -= wv; break;
                default: hi -= wv; break;
            }
        }
        Ar[r][c] = hi;
        Ai[r][c] = -hr;
    }
    __syncthreads();

    // ---- Phase 3: w-series + amp on lanes 0-7 of warp 0 (shuffle matvec) ----
    if (tid < 8) {
        const int j = tid;
        float ar8[8], ai8[8];
        #pragma unroll
        for (int m = 0; m < 8; ++m) { ar8[m] = Ar[j][m]; ai8[m] = Ai[j][m]; }
        float wr = (j == 0) ? 1.0f : 0.0f, wi = 0.0f;
        Wr[0][j] = wr; Wi[0][j] = wi;
        float sumr = wr, sumi = wi;
        #pragma unroll
        for (int n = 1; n <= NTAY; ++n) {
            float accr = 0.f, acci = 0.f;
            #pragma unroll
            for (int m = 0; m < 8; ++m) {
                float xr = __shfl_sync(0x000000FFu, wr, m);
                float xi = __shfl_sync(0x000000FFu, wi, m);
                accr += ar8[m]*xr - ai8[m]*xi;
                acci += ar8[m]*xi + ai8[m]*xr;
            }
            float rn = 1.0f / (float)n;
            wr = accr * rn; wi = acci * rn;
            Wr[n][j] = wr; Wi[n][j] = wi;
            sumr += wr; sumi += wi;
        }
        float P = sumr*sumr + sumi*sumi;
        sAmpR[j] = sumr; sAmpI[j] = sumi;
        sSip[j] = rsqrtf(P);
    }
    __syncthreads();

    // ---- Phase 4: directional derivatives. thread = (k = tid>>3, r = tid&7) ----
    {
        const int k = tid >> 3;        // Pauli direction
        const int r = tid & 7;         // state component
        const int lane = tid & 31;
        const int base = lane & 24;    // 8-lane direction group within warp

        int d0 = (k>>4)&3, d1 = (k>>2)&3, d2 = k&3;
        int mask = ((d0==1||d0==2)?4:0) | ((d1==1||d1==2)?2:0) | ((d2==1||d2==2)?1:0);
        int ph = 0;
        {
            int rb2=(r>>2)&1, rb1=(r>>1)&1, rb0=r&1;
            if (d0==2) ph += rb2?1:3; else if (d0==3) ph += rb2?2:0;
            if (d1==2) ph += rb1?1:3; else if (d1==3) ph += rb1?2:0;
            if (d2==2) ph += rb0?1:3; else if (d2==3) ph += rb0?2:0;
        }
        const int phs = (ph + 3) & 3;        // extra *(-i) from dA = -i P_k
        const int rx = r ^ mask;

        float ar8[8], ai8[8];
        #pragma unroll
        for (int m = 0; m < 8; ++m) { ar8[m] = Ar[r][m]; ai8[m] = Ai[r][m]; }

        float phr = 0.f, phi_ = 0.f;
        float dsr = 0.f, dsi = 0.f;

        #pragma unroll
        for (int n = 1; n <= NTAY; ++n) {
            float accr = 0.f, acci = 0.f;
            #pragma unroll
            for (int m = 0; m < 8; ++m) {
                float xr = __shfl_sync(0xFFFFFFFFu, phr,  base | m);
                float xi = __shfl_sync(0xFFFFFFFFu, phi_, base | m);
                accr += ar8[m]*xr - ai8[m]*xi;
                acci += ar8[m]*xi + ai8[m]*xr;
            }
            float wvr = Wr[n-1][rx], wvi = Wi[n-1][rx];
            float tr, ti;
            if      (phs == 0) { tr =  wvr; ti =  wvi; }
            else if (phs == 1) { tr = -wvi; ti =  wvr; }
            else if (phs == 2) { tr = -wvr; ti = -wvi; }
            else               { tr =  wvi; ti = -wvr; }
            float rn = 1.0f / (float)n;
            phr  = (accr + tr) * rn;
            phi_ = (acci + ti) * rn;
            dsr += phr; dsi += phi_;
        }

        float g = 2.0f * (sAmpR[r]*dsr + sAmpI[r]*dsi);
        g_hmat[(size_t)i*512 + r*64 + k] = g * sSip[r];
    }
}

// ======================= Kernel B: fused Gram + streaming store =======================
// grid = 256 samples x 4 a-quarters; block = 256 threads; thread = (a, b4) float4 unit.
__global__ __launch_bounds__(256)
void out_kernel(const float* __restrict__ x,
                float* __restrict__ out)
{
    const int i  = blockIdx.x >> 2;
    const int qa = blockIdx.x & 3;
    const int tid = threadIdx.x;

    __shared__ float hmat[8][64];

    // load hmat tile (512 floats = 128 float4)
    if (tid < 128) {
        const float4* hsrc = (const float4*)(g_hmat + (size_t)i*512);
        ((float4*)&hmat[0][0])[tid] = hsrc[tid];
    }

    // xx[j][l] in registers
    const float4 xv = ((const float4*)x)[i];
    float xa[4] = {xv.x, xv.y, xv.z, xv.w};
    __syncthreads();

    const int a  = (qa << 4) | (tid >> 4);   // 0..63
    const int b4 = tid & 15;                 // float4 index within b

    // ib4 = Ib[a][b4*4 .. b4*4+3] = sum_p h[p][a] * h[p][b4*4..]
    const float4* hm4 = (const float4*)&hmat[0][0];   // [p*16 + b4]
    float4 ib = make_float4(0.f, 0.f, 0.f, 0.f);
    #pragma unroll
    for (int p = 0; p < 8; ++p) {
        float ha = hmat[p][a];
        float4 hb = hm4[p*16 + b4];
        ib.x += ha*hb.x; ib.y += ha*hb.y; ib.z += ha*hb.z; ib.w += ha*hb.w;
    }

    // I_b store (each (a,b4) owned by exactly one thread across the 4 qa-blocks)
    {
        float4* outb = (float4*)(out + (size_t)256*65536) + (size_t)i*1024;
        outb[a*16 + b4] = ib;
    }

    // I_k stores: 16 scaled copies. addr(float4) = j*4096 + a*64 + l*16 + b4
    {
        float4* outk = (float4*)out + (size_t)i*16384;
        #pragma unroll
        for (int j = 0; j < 4; ++j) {
            float xj = xa[j];
            float4* oj = outk + j*4096 + a*64 + b4;
            #pragma unroll
            for (int l = 0; l < 4; ++l) {
                float sxx = xj * xa[l];
                float4 v;
                v.x = ib.x*sxx; v.y = ib.y*sxx; v.z = ib.z*sxx; v.w = ib.w*sxx;
                oj[l*16] = v;
            }
        }
    }
}

extern "C" void kernel_launch(void* const* d_in, const int* in_sizes, int n_in,
                              void* d_out, int out_size) {
    const float* x = nullptr; const float* k = nullptr; const float* b = nullptr;
    for (int t = 0; t < n_in; ++t) {
        if (in_sizes[t] == 1024 && !x) x = (const float*)d_in[t];
        else if (in_sizes[t] == 256 && !k) k = (const float*)d_in[t];
        else if (in_sizes[t] == 64 && !b) b = (const float*)d_in[t];
    }
    if (!x) x = (const float*)d_in[0];
    if (!k) k = (const float*)d_in[1];
    if (!b) b = (const float*)d_in[2];
    tay_kernel<<<256, 512>>>(x, k, b);
    out_kernel<<<1024, 256>>>(x, (float*)d_out);
}

// round 9
// speedup vs baseline: 1.8672x; 1.1635x over previous
#include <cuda_runtime.h>

// FIStateProbabilitiesPaulied: B=256, ND=4, NQ=3 -> D=8, L=64.
// Single fused kernel, grid 256 x 512 (one block per sample):
//   1. pw = x@kernel+bias, A = -iH built analytically (smem)
//   2. Taylor w-series (8 lanes, shuffle matvec), amp + 1/sqrt(P)
//   3. Frechet directional derivative per (k=tid>>3, r=tid&7), shuffle recursion -> hmat smem
//   4. Fused Gram+store: thread owns two (a,b4) float4 units of I_b; computes in registers,
//      emits 16 scaled I_k stores + 1 I_b store each.
// Output layout: I_k [256*4*64*4*64] then I_b [256*64*64].

#define NTAY 14

__global__ __launch_bounds__(512)
void fi_fused_kernel(const float* __restrict__ x,
                     const float* __restrict__ kern,
                     const float* __restrict__ bias,
                     float* __restrict__ out)
{
    const int i = blockIdx.x;
    const int tid = threadIdx.x;   // 512 threads

    __shared__ float pw[64];
    __shared__ float Ar[8][8], Ai[8][8];            // A = -iH
    __shared__ float Wr[NTAY+1][8], Wi[NTAY+1][8];  // w_n = A^n e0 / n!
    __shared__ float sAmpR[8], sAmpI[8], sSip[8];
    __shared__ float hmat[8][64];                   // h[r][k]

    // ---- Phase 1: pw = x@kernel + bias ----
    if (tid < 64) {
        float acc = bias[tid];
        #pragma unroll
        for (int d = 0; d < 4; ++d) acc += x[i*4+d] * kern[d*64+tid];
        pw[tid] = acc;
    }
    __syncthreads();

    // ---- Phase 2: build H analytically; store A = -iH (Ar=Hi, Ai=-Hr) ----
    if (tid < 64) {
        int r = tid >> 3, c = tid & 7, m = r ^ c;
        float hr = 0.0f, hi = 0.0f;
        #pragma unroll
        for (int sel = 0; sel < 8; ++sel) {
            int k = 0, ph = 0;
            #pragma unroll
            for (int q = 0; q < 3; ++q) {
                int bit = 2 - q;
                int mq = (m >> bit) & 1;
                int sq = (sel >> bit) & 1;
                int d = mq ? (sq ? 2 : 1) : (sq ? 3 : 0);
                k = (k << 2) | d;
                int rb = (r >> bit) & 1;
                if (d == 2) ph += rb ? 1 : 3;        // Y
                else if (d == 3) ph += rb ? 2 : 0;   // Z
            }
            float wv = pw[k];
            switch (ph & 3) {
                case 0: hr += wv; break;
                case 1: hi += wv; break;
                case 2: hr -= wv; break;
                default: hi -= wv; break;
            }
        }
        Ar[r][c] = hi;
        Ai[r][c] = -hr;
    }
    __syncthreads();

    // ---- Phase 3: w-series + amp on lanes 0-7 of warp 0 (shuffle matvec) ----
    if (tid < 8) {
        const int j = tid;
        float ar8[8], ai8[8];
        #pragma unroll
        for (int m = 0; m < 8; ++m) { ar8[m] = Ar[j][m]; ai8[m] = Ai[j][m]; }
        float wr = (j == 0) ? 1.0f : 0.0f, wi = 0.0f;
        Wr[0][j] = wr; Wi[0][j] = wi;
        float sumr = wr, sumi = wi;
        #pragma unroll
        for (int n = 1; n <= NTAY; ++n) {
            float accr = 0.f, acci = 0.f;
            #pragma unroll
            for (int m = 0; m < 8; ++m) {
                float xr = __shfl_sync(0x000000FFu, wr, m);
                float xi = __shfl_sync(0x000000FFu, wi, m);
                accr += ar8[m]*xr - ai8[m]*xi;
                acci += ar8[m]*xi + ai8[m]*xr;
            }
            const float rn = 1.0f / (float)n;       // compile-time constant (unrolled)
            wr = accr * rn; wi = acci * rn;
            Wr[n][j] = wr; Wi[n][j] = wi;
            sumr += wr; sumi += wi;
        }
        float P = sumr*sumr + sumi*sumi;
        sAmpR[j] = sumr; sAmpI[j] = sumi;
        sSip[j] = rsqrtf(P);
    }
    __syncthreads();

    // ---- Phase 4: directional derivatives. thread = (k = tid>>3, r = tid&7) ----
    {
        const int k = tid >> 3;        // Pauli direction
        const int r = tid & 7;         // state component
        const int lane = tid & 31;
        const int base = lane & 24;    // 8-lane direction group within warp

        int d0 = (k>>4)&3, d1 = (k>>2)&3, d2 = k&3;
        int mask = ((d0==1||d0==2)?4:0) | ((d1==1||d1==2)?2:0) | ((d2==1||d2==2)?1:0);
        int ph = 0;
        {
            int rb2=(r>>2)&1, rb1=(r>>1)&1, rb0=r&1;
            if (d0==2) ph += rb2?1:3; else if (d0==3) ph += rb2?2:0;
            if (d1==2) ph += rb1?1:3; else if (d1==3) ph += rb1?2:0;
            if (d2==2) ph += rb0?1:3; else if (d2==3) ph += rb0?2:0;
        }
        const int phs = (ph + 3) & 3;        // extra *(-i) from dA = -i P_k
        const int rx = r ^ mask;

        float ar8[8], ai8[8];
        #pragma unroll
        for (int m = 0; m < 8; ++m) { ar8[m] = Ar[r][m]; ai8[m] = Ai[r][m]; }

        float phr = 0.f, phi_ = 0.f;
        float dsr = 0.f, dsi = 0.f;

        #pragma unroll
        for (int n = 1; n <= NTAY; ++n) {
            float accr = 0.f, acci = 0.f;
            #pragma unroll
            for (int m = 0; m < 8; ++m) {
                float xr = __shfl_sync(0xFFFFFFFFu, phr,  base | m);
                float xi = __shfl_sync(0xFFFFFFFFu, phi_, base | m);
                accr += ar8[m]*xr - ai8[m]*xi;
                acci += ar8[m]*xi + ai8[m]*xr;
            }
            float wvr = Wr[n-1][rx], wvi = Wi[n-1][rx];
            float tr, ti;
            if      (phs == 0) { tr =  wvr; ti =  wvi; }
            else if (phs == 1) { tr = -wvi; ti =  wvr; }
            else if (phs == 2) { tr = -wvr; ti = -wvi; }
            else               { tr =  wvi; ti = -wvr; }
            const float rn = 1.0f / (float)n;
            phr  = (accr + tr) * rn;
            phi_ = (acci + ti) * rn;
            dsr += phr; dsi += phi_;
        }

        float g = 2.0f * (sAmpR[r]*dsr + sAmpI[r]*dsi);
        hmat[r][k] = g * sSip[r];
    }

    // xx in registers while waiting
    const float4 xv = ((const float4*)x)[i];
    float xa[4] = {xv.x, xv.y, xv.z, xv.w};
    __syncthreads();

    // ---- Phase 5: fused Gram + streaming store ----
    // 1024 (a,b4) units, 512 threads -> 2 units/thread.
    const float4* hm4 = (const float4*)&hmat[0][0];   // [p*16 + b4]
    float4* outk_base = (float4*)out + (size_t)i*16384;
    float4* outb = (float4*)(out + (size_t)256*65536) + (size_t)i*1024;

    #pragma unroll
    for (int u = 0; u < 2; ++u) {
        const int unit = tid + 512*u;
        const int a  = unit >> 4;     // 0..63
        const int b4 = unit & 15;     // float4 index within b

        float4 ib = make_float4(0.f, 0.f, 0.f, 0.f);
        #pragma unroll
        for (int p = 0; p < 8; ++p) {
            float ha = hmat[p][a];
            float4 hb = hm4[p*16 + b4];
            ib.x += ha*hb.x; ib.y += ha*hb.y; ib.z += ha*hb.z; ib.w += ha*hb.w;
        }

        // I_b store
        outb[a*16 + b4] = ib;

        // I_k stores: addr(float4) = j*4096 + a*64 + l*16 + b4
        float4* oj = outk_base + a*64 + b4;
        #pragma unroll
        for (int j = 0; j < 4; ++j) {
            float xj = xa[j];
            #pragma unroll
            for (int l = 0; l < 4; ++l) {
                float sxx = xj * xa[l];
                float4 v;
                v.x = ib.x*sxx; v.y = ib.y*sxx; v.z = ib.z*sxx; v.w = ib.w*sxx;
                oj[j*4096 + l*16] = v;
            }
        }
    }
}

extern "C" void kernel_launch(void* const* d_in, const int* in_sizes, int n_in,
                              void* d_out, int out_size) {
    const float* x = nullptr; const float* k = nullptr; const float* b = nullptr;
    for (int t = 0; t < n_in; ++t) {
        if (in_sizes[t] == 1024 && !x) x = (const float*)d_in[t];
        else if (in_sizes[t] == 256 && !k) k = (const float*)d_in[t];
        else if (in_sizes[t] == 64 && !b) b = (const float*)d_in[t];
    }
    if (!x) x = (const float*)d_in[0];
    if (!k) k = (const float*)d_in[1];
    if (!b) b = (const float*)d_in[2];
    fi_fused_kernel<<<256, 512>>>(x, k, b, (float*)d_out);
}

// round 13
// speedup vs baseline: 2.0082x; 1.0755x over previous
#include <cuda_runtime.h>

// FIStateProbabilitiesPaulied: B=256, ND=4, NQ=3 -> D=8, L=64.
// Single fused kernel, grid 256 x 512 (one block per sample).
// Factored Frechet: damp_k = sum_j G~_j dA_k S~_j with G~_j = A^j/j!,
// S~_j = sum_l c_{j,l} u~_l, c_{j,l} = j! l!/(j+l+1)!, u~_l = G~_l[:,0].
// g[p][k] = 2 sum_m Re( i^phs(m,k) * C[p][m][m^mask_k] ),
// C[p][m][m'] = conj(amp_p) * sum_j G~_j[p][m] S~_j[m'].
// Series complete through n = NJ (tail ~3e-9 at ||A||~3.2).
// Output layout: I_k [256*4*64*4*64] then I_b [256*64*64].
// R11 fix: __align__(16) on float4-accessed shared arrays (hmat) — the cjl
// array (361 floats) shifted the smem layout and LDS.128 on hmat trapped.

#define NJ 19   // j,l = 0..NJ-1

__global__ __launch_bounds__(512)
void fi_fused_kernel(const float* __restrict__ x,
                     const float* __restrict__ kern,
                     const float* __restrict__ bias,
                     float* __restrict__ out)
{
    const int i = blockIdx.x;
    const int tid = threadIdx.x;   // 512 threads

    __shared__ float pw[64];
    __shared__ float Ar[8][8], Ai[8][8];       // A = -iH
    __shared__ float cjl[NJ][NJ];              // j! l! / (j+l+1)!
    __shared__ __align__(16) float Gr[NJ][8][8], Gi[NJ][8][8];   // G~_j = A^j / j!
    __shared__ float Sr[NJ][8], Si[NJ][8];     // S~_j
    __shared__ float ampr[8], ampi[8], sIpS[8];
    __shared__ float Cr[8][8][8], Ci[8][8][8]; // [m][mp][p]
    __shared__ __align__(16) float hmat[8][64];  // h[p][k]  (float4-accessed)

    // ---- Phase 1: pw = x@kernel + bias; c_{j,l} table ----
    if (tid < 64) {
        float acc = bias[tid];
        #pragma unroll
        for (int d = 0; d < 4; ++d) acc += x[i*4+d] * kern[d*64+tid];
        pw[tid] = acc;
    } else if (tid >= 128 && tid < 128 + NJ*NJ) {
        int t = tid - 128;
        int j = t / NJ, l = t % NJ;
        float c = 1.f;
        for (int s = 1; s <= l; ++s) c *= (float)s / (float)(j + s);
        cjl[j][l] = c / (float)(j + l + 1);
    }
    __syncthreads();

    // ---- Phase 2: A = -iH (analytic Pauli build); G~_0 = I ----
    if (tid < 64) {
        int r = tid >> 3, c = tid & 7, m = r ^ c;
        float hr = 0.0f, hi = 0.0f;
        #pragma unroll
        for (int sel = 0; sel < 8; ++sel) {
            int k = 0, ph = 0;
            #pragma unroll
            for (int q = 0; q < 3; ++q) {
                int bit = 2 - q;
                int mq = (m >> bit) & 1;
                int sq = (sel >> bit) & 1;
                int d = mq ? (sq ? 2 : 1) : (sq ? 3 : 0);
                k = (k << 2) | d;
                int rb = (r >> bit) & 1;
                if (d == 2) ph += rb ? 1 : 3;        // Y
                else if (d == 3) ph += rb ? 2 : 0;   // Z
            }
            float wv = pw[k];
            switch (ph & 3) {
                case 0: hr += wv; break;
                case 1: hi += wv; break;
                case 2: hr -= wv; break;
                default: hi -= wv; break;
            }
        }
        Ar[r][c] = hi;
        Ai[r][c] = -hr;
        Gr[0][r][c] = (r == c) ? 1.0f : 0.0f;
        Gi[0][r][c] = 0.0f;
    }
    __syncthreads();

    // ---- Phase 3: G~ chain: G~_{j+1} = A G~_j / (j+1) ----
    for (int j = 0; j < NJ-1; ++j) {
        if (tid < 64) {
            int r = tid >> 3, c = tid & 7;
            float accr = 0.f, acci = 0.f;
            #pragma unroll
            for (int m = 0; m < 8; ++m) {
                float gr = Gr[j][m][c], gi = Gi[j][m][c];
                float ar = Ar[r][m],  ai = Ai[r][m];
                accr += ar*gr - ai*gi;
                acci += ar*gi + ai*gr;
            }
            float rn = 1.0f / (float)(j + 1);
            Gr[j+1][r][c] = accr * rn;
            Gi[j+1][r][c] = acci * rn;
        }
        __syncthreads();
    }

    // ---- Phase 4: S~_j[r] (tid<NJ*8) ; amp, 1/sqrt(P) (tid 256..263) ----
    if (tid < NJ*8) {
        int j = tid >> 3, r = tid & 7;
        float sr = 0.f, si = 0.f;
        #pragma unroll
        for (int l = 0; l < NJ; ++l) {
            float c = cjl[j][l];
            sr += c * Gr[l][r][0];     // u~_l[r] = G~_l[r][0]
            si += c * Gi[l][r][0];
        }
        Sr[j][r] = sr; Si[j][r] = si;
    }
    if (tid >= 256 && tid < 264) {
        int r = tid - 256;
        float ar = 0.f, ai = 0.f;
        #pragma unroll
        for (int j = 0; j < NJ; ++j) { ar += Gr[j][r][0]; ai += Gi[j][r][0]; }
        ampr[r] = ar; ampi[r] = ai;
        sIpS[r] = rsqrtf(ar*ar + ai*ai);
    }
    __syncthreads();

    // ---- Phase 5: C[m][mp][p] = conj(amp_p) * sum_j G~_j[p][m] S~_j[mp] ----
    {
        int m  = tid >> 6;
        int mp = (tid >> 3) & 7;
        int p  = tid & 7;
        float dr = 0.f, di = 0.f;
        #pragma unroll
        for (int j = 0; j < NJ; ++j) {
            float gr = Gr[j][p][m], gi = Gi[j][p][m];
            float sr = Sr[j][mp],   si = Si[j][mp];
            dr += gr*sr - gi*si;
            di += gr*si + gi*sr;
        }
        float ar = ampr[p], ai = ampi[p];
        Cr[m][mp][p] = ar*dr + ai*di;    // Re(conj(amp)*D)
        Ci[m][mp][p] = ar*di - ai*dr;    // Im(conj(amp)*D)
    }
    __syncthreads();

    // ---- Phase 6: h[p][k] = 2 * sIp[p] * sum_m Re(i^phs(m,k) C[p][m][m^mask]) ----
    {
        const int k = tid >> 3;
        const int p = tid & 7;
        int d0 = (k>>4)&3, d1 = (k>>2)&3, d2 = k&3;
        int mask = ((d0==1||d0==2)?4:0) | ((d1==1||d1==2)?2:0) | ((d2==1||d2==2)?1:0);
        float g = 0.f;
        #pragma unroll
        for (int m = 0; m < 8; ++m) {
            int ph = 0;
            int b2=(m>>2)&1, b1=(m>>1)&1, b0=m&1;
            if (d0==2) ph += b2?1:3; else if (d0==3) ph += b2?2:0;
            if (d1==2) ph += b1?1:3; else if (d1==3) ph += b1?2:0;
            if (d2==2) ph += b0?1:3; else if (d2==3) ph += b0?2:0;
            int phs = (ph + 3) & 3;              // includes the -i of dA = -i P_k
            float cr = Cr[m][m^mask][p];
            float ci = Ci[m][m^mask][p];
            // Re( i^phs * (cr + i ci) )
            float term = (phs == 0) ? cr : (phs == 1) ? -ci : (phs == 2) ? -cr : ci;
            g += term;
        }
        hmat[p][k] = 2.0f * g * sIpS[p];
    }

    const float4 xv = ((const float4*)x)[i];
    float xa[4] = {xv.x, xv.y, xv.z, xv.w};
    __syncthreads();

    // ---- Phase 7: fused Gram + streaming store (2 (a,b4) units per thread) ----
    const float4* hm4 = (const float4*)&hmat[0][0];   // [p*16 + b4]
    float4* outk_base = (float4*)out + (size_t)i*16384;
    float4* outb = (float4*)(out + (size_t)256*65536) + (size_t)i*1024;

    #pragma unroll
    for (int u = 0; u < 2; ++u) {
        const int unit = tid + 512*u;
        const int a  = unit >> 4;     // 0..63
        const int b4 = unit & 15;     // float4 index within b

        float4 ib = make_float4(0.f, 0.f, 0.f, 0.f);
        #pragma unroll
        for (int p = 0; p < 8; ++p) {
            float ha = hmat[p][a];
            float4 hb = hm4[p*16 + b4];
            ib.x += ha*hb.x; ib.y += ha*hb.y; ib.z += ha*hb.z; ib.w += ha*hb.w;
        }

        // I_b store
        outb[a*16 + b4] = ib;

        // I_k stores: addr(float4) = j*4096 + a*64 + l*16 + b4
        float4* oj = outk_base + a*64 + b4;
        #pragma unroll
        for (int j = 0; j < 4; ++j) {
            float xj = xa[j];
            #pragma unroll
            for (int l = 0; l < 4; ++l) {
                float sxx = xj * xa[l];
                float4 v;
                v.x = ib.x*sxx; v.y = ib.y*sxx; v.z = ib.z*sxx; v.w = ib.w*sxx;
                oj[j*4096 + l*16] = v;
            }
        }
    }
}

extern "C" void kernel_launch(void* const* d_in, const int* in_sizes, int n_in,
                              void* d_out, int out_size) {
    const float* x = nullptr; const float* k = nullptr; const float* b = nullptr;
    for (int t = 0; t < n_in; ++t) {
        if (in_sizes[t] == 1024 && !x) x = (const float*)d_in[t];
        else if (in_sizes[t] == 256 && !k) k = (const float*)d_in[t];
        else if (in_sizes[t] == 64 && !b) b = (const float*)d_in[t];
    }
    if (!x) x = (const float*)d_in[0];
    if (!k) k = (const float*)d_in[1];
    if (!b) b = (const float*)d_in[2];
    fi_fused_kernel<<<256, 512>>>(x, k, b, (float*)d_out);
}